// round 15
// baseline (speedup 1.0000x reference)
#include <cuda_runtime.h>
#include <cuda_bf16.h>
#include <cstdint>

// ---------------------------------------------------------------------------
// Compile-time normalization constants K(l,m) baked in as immediates:
//   K = sqrt((2l+1)/(4pi) * (l-m)!/(l+m)!),   times sqrt(2) for m != 0
// ---------------------------------------------------------------------------
namespace {

constexpr double csqrt(double x) {
    double g = x > 1.0 ? x : 1.0;
    for (int i = 0; i < 100; i++) g = 0.5 * (g + x / g);
    return g;
}
constexpr double dfact(int n) {
    double r = 1.0;
    for (int i = 2; i <= n; i++) r *= (double)i;
    return r;
}
constexpr double PI_D = 3.14159265358979323846;

struct KTab { float c[8][8]; };

constexpr KTab mk_ktab() {
    KTab t{};
    for (int l = 0; l < 8; l++)
        for (int m = 0; m <= l; m++) {
            double K = csqrt((2.0 * l + 1.0) / (4.0 * PI_D)
                             * dfact(l - m) / dfact(l + m));
            if (m > 0) K *= csqrt(2.0);
            t.c[l][m] = (float)K;
        }
    return t;
}

__device__ constexpr KTab g_Kc = mk_ktab();

} // namespace

// ---------------------------------------------------------------------------
// FINAL (champion, R8): l-outer pipeline with a 2-slot SMEM ring buffer.
// One block = 256 points. Slot = largest region (15*TPB floats, 15 KB);
// 2 slots = 30.7 KB => 6 blocks/SM, ~64% occupancy.
// Region l (l=1..7) staged in slot (l&1) in OUTPUT order: element (pt, j)
// at pt*w + j (lane stride w odd => conflict-free bank permutation).
// After a barrier, thread 0 issues ONE cp.async.bulk shared->global
// (1.5..15 KB, both sides 16B-aligned) and wait_group 1: the slot reused
// next iteration (copy issued two regions ago) is guaranteed drained.
// l = 0 is the constant Y00 = 1/sqrt(4pi) (direct coalesced store).
// Measured: 80.4 us = ~6.6 TB/s sustained, at the HBM3e write ceiling
// (seven structural variants all converge to 78.3-78.5 us ncu).
// ---------------------------------------------------------------------------
constexpr int TPB = 256;
constexpr int SLOT_FLOATS = 15 * TPB;          // largest region (l=7)

__device__ __forceinline__ uint32_t smem_u32(const void* p) {
    uint32_t a;
    asm("{ .reg .u64 t; cvta.to.shared.u64 t, %1; cvt.u32.u64 %0, t; }"
        : "=r"(a) : "l"(p));
    return a;
}

__global__ __launch_bounds__(TPB, 6)
void sph_harm_kernel(const float* __restrict__ cos_theta,
                     const float* __restrict__ phi,
                     float* __restrict__ out,
                     int N)
{
    __shared__ float slot[2][SLOT_FLOATS];     // 30720 B

    const int t  = threadIdx.x;
    const long long bs = (long long)blockIdx.x * TPB;
    const int n    = (int)bs + t;
    const int rows = (int)min((long long)TPB, (long long)N - bs);
    const bool full = (rows == TPB) && ((N & 3) == 0);

    const int nc = (n < N) ? n : (N - 1);

    const float x = cos_theta[nc];
    const float p = phi[nc];
    const float s = sqrtf(fmaxf(1.0f - x * x, 0.0f));

    float sp, cp;
    __sincosf(p, &sp, &cp);

    // l = 0 : Y00 is a constant.
    if (n < N) out[n] = g_Kc.c[0][0];

    // Recurrence state (fully unrolled -> registers).
    float Pp[8];    // P_{l-1}^m
    float Ppp[8];   // P_{l-2}^m
    float cmv[8], smv[8];
    Pp[0] = 1.0f;
    cmv[0] = 1.0f; smv[0] = 0.0f;

    #pragma unroll
    for (int l = 1; l <= 7; l++) {
        float Pl[8];
        #pragma unroll
        for (int m = 0; m <= l - 2; m++)
            Pl[m] = ((2.0f * l - 1.0f) * x * Pp[m]
                     - (float)(l + m - 1) * Ppp[m]) * (1.0f / (float)(l - m));
        Pl[l - 1] = (2.0f * l - 1.0f) * x * Pp[l - 1];
        Pl[l]     = -(2.0f * l - 1.0f) * s * Pp[l - 1];   // Condon-Shortley

        cmv[l] = cp * cmv[l - 1] - sp * smv[l - 1];
        smv[l] = sp * cmv[l - 1] + cp * smv[l - 1];

        const int w = 2 * l + 1;
        float* buf = slot[l & 1];

        // stage region l (lane stride w odd -> conflict-free)
        {
            const int base = t * w;
            buf[base + l] = g_Kc.c[l][0] * Pl[0];
            #pragma unroll
            for (int m = 1; m <= l; m++) {
                const float kp = g_Kc.c[l][m] * Pl[m];
                buf[base + (l - m)] = kp * smv[m];
                buf[base + (l + m)] = kp * cmv[m];
            }
        }

        __syncthreads();                       // region staged

        if (full) {
            if (t == 0) {
                asm volatile("fence.proxy.async.shared::cta;" ::: "memory");
                const uint32_t src = smem_u32(buf);
                float* dstp = out + (size_t)N * (size_t)(l * l)
                                  + (size_t)bs * (size_t)w;
                const uint32_t bytes = (uint32_t)(TPB * w * 4);
                asm volatile(
                    "cp.async.bulk.global.shared::cta.bulk_group [%0], [%1], %2;"
                    :: "l"(dstp), "r"(src), "r"(bytes) : "memory");
                asm volatile("cp.async.bulk.commit_group;" ::: "memory");
                // allow 1 outstanding group: the copy issued for region l-1
                // (into the OTHER slot) may still fly; the one from l-2
                // (this slot) must have drained before we overwrite it.
                asm volatile("cp.async.bulk.wait_group 1;" ::: "memory");
            }
        } else {
            // tail / unaligned fallback (one block at N = 2M)
            float* dst = out + (size_t)N * (size_t)(l * l)
                             + (size_t)bs * (size_t)w;
            const int cnt = rows * w;
            for (int i = t; i < cnt; i += TPB)
                dst[i] = buf[i];
        }

        __syncthreads();                       // slot-reuse safety

        #pragma unroll
        for (int m = 0; m <= l - 1; m++) Ppp[m] = Pp[m];
        #pragma unroll
        for (int m = 0; m <= l; m++)     Pp[m]  = Pl[m];
    }

    if (full && t == 0)
        asm volatile("cp.async.bulk.wait_group 0;" ::: "memory");
}

extern "C" void kernel_launch(void* const* d_in, const int* in_sizes, int n_in,
                              void* d_out, int out_size)
{
    const float* cos_theta = (const float*)d_in[0];
    const float* phi       = (const float*)d_in[1];
    float* out             = (float*)d_out;
    const int N = in_sizes[0];

    const int blocks = (N + TPB - 1) / TPB;
    sph_harm_kernel<<<blocks, TPB>>>(cos_theta, phi, out, N);
}